// round 2
// baseline (speedup 1.0000x reference)
#include <cuda_runtime.h>

#define CH 64
#define NMAX 100000
#define EMAX 1200000
#define SCAN_B 1024

// Scratch (allocation-free rule: __device__ globals)
__device__ float g_h1[NMAX * CH];
__device__ int   g_deg[NMAX];
__device__ int   g_cur[NMAX];
__device__ int   g_rowptr[NMAX + 1];
__device__ int   g_csr[EMAX];
__device__ int   g_bsum[128];
__device__ int   g_boff[128];
__device__ int   g_is64;

// ---------------------------------------------------------------------------
// Detect int64 vs int32 edge_index. If data is really int32, int64 reads
// combine two indices -> huge values with overwhelming probability.
// ---------------------------------------------------------------------------
__global__ void detect_idx_kernel(const void* idx, int nNodes) {
    if (threadIdx.x == 0 && blockIdx.x == 0) {
        const long long* p = (const long long*)idx;
        int is64 = 1;
        for (int i = 0; i < 1024; i++) {
            long long v = p[i];
            if (v < 0 || v >= (long long)nNodes) { is64 = 0; break; }
        }
        g_is64 = is64;
    }
}

__global__ void zero_int_kernel(int n) {
    int i = blockIdx.x * blockDim.x + threadIdx.x;
    if (i < n) { g_deg[i] = 0; g_cur[i] = 0; }
}

__device__ __forceinline__ void load_edge(const void* idx, int nEdges, int e,
                                          int& s, int& d) {
    if (g_is64) {
        const long long* p = (const long long*)idx;
        s = (int)p[e];
        d = (int)p[nEdges + e];
    } else {
        const int* p = (const int*)idx;
        s = p[e];
        d = p[nEdges + e];
    }
}

__global__ void count_kernel(const void* __restrict__ idx, int nEdges) {
    int e = blockIdx.x * blockDim.x + threadIdx.x;
    if (e >= nEdges) return;
    int s, d;
    load_edge(idx, nEdges, e, s, d);
    atomicAdd(&g_deg[d], 1);
}

// ---- 3-phase exclusive scan of g_deg into g_rowptr -------------------------
__global__ void scan_block_kernel(int n) {
    __shared__ int sh[SCAN_B];
    int i = blockIdx.x * SCAN_B + threadIdx.x;
    int v = (i < n) ? g_deg[i] : 0;
    sh[threadIdx.x] = v;
    __syncthreads();
    for (int off = 1; off < SCAN_B; off <<= 1) {
        int t = (threadIdx.x >= off) ? sh[threadIdx.x - off] : 0;
        __syncthreads();
        sh[threadIdx.x] += t;
        __syncthreads();
    }
    if (i < n) g_rowptr[i] = sh[threadIdx.x] - v;   // exclusive, block-local
    if (threadIdx.x == SCAN_B - 1) g_bsum[blockIdx.x] = sh[SCAN_B - 1];
}

__global__ void scan_top_kernel(int nBlocks, int nEdges, int nNodes) {
    if (threadIdx.x == 0 && blockIdx.x == 0) {
        int run = 0;
        for (int b = 0; b < nBlocks; b++) {
            g_boff[b] = run;
            run += g_bsum[b];
        }
        g_rowptr[nNodes] = nEdges;
    }
}

__global__ void scan_add_kernel(int n) {
    int i = blockIdx.x * SCAN_B + threadIdx.x;
    if (i < n) g_rowptr[i] += g_boff[blockIdx.x];
}

__global__ void fill_kernel(const void* __restrict__ idx, int nEdges) {
    int e = blockIdx.x * blockDim.x + threadIdx.x;
    if (e >= nEdges) return;
    int s, d;
    load_edge(idx, nEdges, e, s, d);
    int pos = atomicAdd(&g_cur[d], 1);
    g_csr[g_rowptr[d] + pos] = s;
}

// ---------------------------------------------------------------------------
// Fused gather + SAGE conv:
//   mean_n = (1/max(deg,1)) * sum_{e in CSR[n]} feat[src_e]
//   h_n    = relu(mean_n @ Wl + b + feat_n @ Wr)
//   layer 1: feat = x (NaN-fixed), writes g_h1
//   layer 2: feat = g_h1, fuses pred_n = h_n @ Wfc + bfc (h2 never stored)
// 256 threads = 32 nodes x 8 lanes; each lane owns 8 channels. Mean and root
// features live in registers, exchanged via shfl during the GEMV. Weights
// staged once per (persistent) block in smem.
// ---------------------------------------------------------------------------
__global__ void __launch_bounds__(256, 3)
conv_kernel(const float* __restrict__ x,
            const float* __restrict__ Wl,
            const float* __restrict__ bias,
            const float* __restrict__ Wr,
            const float* __restrict__ Wfc,
            const float* __restrict__ bfc,
            float* __restrict__ pred,
            int nNodes, int layer) {
    __shared__ float sWl[CH * CH];
    __shared__ float sWr[CH * CH];
    __shared__ float sB[CH];
    __shared__ float sWfc[CH];

    for (int i = threadIdx.x; i < CH * CH; i += blockDim.x) {
        sWl[i] = Wl[i];
        sWr[i] = Wr[i];
    }
    if (threadIdx.x < CH) {
        sB[threadIdx.x] = bias[threadIdx.x];
        sWfc[threadIdx.x] = (layer == 2) ? Wfc[threadIdx.x] : 0.0f;
    }
    __syncthreads();

    const float* feat = (layer == 1) ? x : g_h1;
    const int grp = threadIdx.x >> 3;            // node slot in block (0..31)
    const int jg  = threadIdx.x & 7;             // channel group (0..7)
    const int j0  = jg * 8;
    const int baseLane = (threadIdx.x & 31) & ~7;  // first lane of 8-group

    for (int tile = blockIdx.x * 32; tile < nNodes; tile += gridDim.x * 32) {
        int node = tile + grp;
        bool valid = node < nNodes;

        float a[8], xr[8];
#pragma unroll
        for (int i = 0; i < 8; i++) { a[i] = 0.0f; xr[i] = 0.0f; }

        if (valid) {
            int r0 = g_rowptr[node];
            int r1 = g_rowptr[node + 1];
            for (int e = r0; e < r1; e++) {
                int s = g_csr[e];
                const float4* f = (const float4*)(feat + (size_t)s * CH + j0);
                float4 f0 = f[0], f1 = f[1];
                if (layer == 1) {
                    if (f0.x != f0.x) f0.x = 0.0f;
                    if (f0.y != f0.y) f0.y = 0.0f;
                    if (f0.z != f0.z) f0.z = 0.0f;
                    if (f0.w != f0.w) f0.w = 0.0f;
                    if (f1.x != f1.x) f1.x = 0.0f;
                    if (f1.y != f1.y) f1.y = 0.0f;
                    if (f1.z != f1.z) f1.z = 0.0f;
                    if (f1.w != f1.w) f1.w = 0.0f;
                }
                a[0] += f0.x; a[1] += f0.y; a[2] += f0.z; a[3] += f0.w;
                a[4] += f1.x; a[5] += f1.y; a[6] += f1.z; a[7] += f1.w;
            }
            int deg = r1 - r0;
            float inv = 1.0f / (float)((deg > 1) ? deg : 1);
#pragma unroll
            for (int i = 0; i < 8; i++) a[i] *= inv;

            const float4* xp = (const float4*)(feat + (size_t)node * CH + j0);
            float4 x0 = xp[0], x1 = xp[1];
            if (layer == 1) {
                if (x0.x != x0.x) x0.x = 0.0f;
                if (x0.y != x0.y) x0.y = 0.0f;
                if (x0.z != x0.z) x0.z = 0.0f;
                if (x0.w != x0.w) x0.w = 0.0f;
                if (x1.x != x1.x) x1.x = 0.0f;
                if (x1.y != x1.y) x1.y = 0.0f;
                if (x1.z != x1.z) x1.z = 0.0f;
                if (x1.w != x1.w) x1.w = 0.0f;
            }
            xr[0] = x0.x; xr[1] = x0.y; xr[2] = x0.z; xr[3] = x0.w;
            xr[4] = x1.x; xr[5] = x1.y; xr[6] = x1.z; xr[7] = x1.w;
        }

        float acc[8];
#pragma unroll
        for (int i = 0; i < 8; i++) acc[i] = sB[j0 + i];

#pragma unroll
        for (int k = 0; k < CH; k++) {
            int srcLane = baseLane + (k >> 3);
            float mk = __shfl_sync(0xffffffffu, a[k & 7], srcLane);
            float xk = __shfl_sync(0xffffffffu, xr[k & 7], srcLane);
            float4 wl0 = *(const float4*)&sWl[k * CH + j0];
            float4 wl1 = *(const float4*)&sWl[k * CH + j0 + 4];
            float4 wr0 = *(const float4*)&sWr[k * CH + j0];
            float4 wr1 = *(const float4*)&sWr[k * CH + j0 + 4];
            acc[0] = fmaf(mk, wl0.x, acc[0]); acc[0] = fmaf(xk, wr0.x, acc[0]);
            acc[1] = fmaf(mk, wl0.y, acc[1]); acc[1] = fmaf(xk, wr0.y, acc[1]);
            acc[2] = fmaf(mk, wl0.z, acc[2]); acc[2] = fmaf(xk, wr0.z, acc[2]);
            acc[3] = fmaf(mk, wl0.w, acc[3]); acc[3] = fmaf(xk, wr0.w, acc[3]);
            acc[4] = fmaf(mk, wl1.x, acc[4]); acc[4] = fmaf(xk, wr1.x, acc[4]);
            acc[5] = fmaf(mk, wl1.y, acc[5]); acc[5] = fmaf(xk, wr1.y, acc[5]);
            acc[6] = fmaf(mk, wl1.z, acc[6]); acc[6] = fmaf(xk, wr1.z, acc[6]);
            acc[7] = fmaf(mk, wl1.w, acc[7]); acc[7] = fmaf(xk, wr1.w, acc[7]);
        }

#pragma unroll
        for (int i = 0; i < 8; i++) acc[i] = fmaxf(acc[i], 0.0f);

        if (layer == 1) {
            if (valid) {
                float* o = g_h1 + (size_t)node * CH + j0;
                *(float4*)o       = make_float4(acc[0], acc[1], acc[2], acc[3]);
                *(float4*)(o + 4) = make_float4(acc[4], acc[5], acc[6], acc[7]);
            }
        } else {
            float p = 0.0f;
#pragma unroll
            for (int i = 0; i < 8; i++) p = fmaf(acc[i], sWfc[j0 + i], p);
            p += __shfl_down_sync(0xffffffffu, p, 4, 8);
            p += __shfl_down_sync(0xffffffffu, p, 2, 8);
            p += __shfl_down_sync(0xffffffffu, p, 1, 8);
            if (jg == 0 && valid) pred[node] = p + bfc[0];
        }
    }
}

// ---------------------------------------------------------------------------
// Launch (graph-capturable: kernel launches only; no allocs, no syncs)
// ---------------------------------------------------------------------------
extern "C" void kernel_launch(void* const* d_in, const int* in_sizes, int n_in,
                              void* d_out, int out_size) {
    const float* x   = (const float*)d_in[0];
    const void*  eix = d_in[1];
    const float* W1l = (const float*)d_in[2];
    const float* b1  = (const float*)d_in[3];
    const float* W1r = (const float*)d_in[4];
    const float* W2l = (const float*)d_in[5];
    const float* b2  = (const float*)d_in[6];
    const float* W2r = (const float*)d_in[7];
    const float* Wfc = (const float*)d_in[8];
    const float* bfc = (const float*)d_in[9];
    float* pred = (float*)d_out;

    int nNodes = in_sizes[0] / CH;   // 100000
    int nEdges = in_sizes[1] / 2;    // 1200000

    int edgeBlocks = (nEdges + 255) / 256;
    int nodeBlocks = (nNodes + 255) / 256;
    int scanBlocks = (nNodes + SCAN_B - 1) / SCAN_B;
    int convGrid   = 888;            // persistent; loops over node tiles

    detect_idx_kernel<<<1, 32>>>(eix, nNodes);

    // Build CSR (dst -> list of src), reused by both layers
    zero_int_kernel<<<nodeBlocks, 256>>>(nNodes);
    count_kernel<<<edgeBlocks, 256>>>(eix, nEdges);
    scan_block_kernel<<<scanBlocks, SCAN_B>>>(nNodes);
    scan_top_kernel<<<1, 32>>>(scanBlocks, nEdges, nNodes);
    scan_add_kernel<<<scanBlocks, SCAN_B>>>(nNodes);
    fill_kernel<<<edgeBlocks, 256>>>(eix, nEdges);

    // Layer 1: gather+conv fused, writes g_h1
    conv_kernel<<<convGrid, 256>>>(x, W1l, b1, W1r, Wfc, bfc, pred, nNodes, 1);
    // Layer 2: gather+conv fused + fc head, writes pred
    conv_kernel<<<convGrid, 256>>>(x, W2l, b2, W2r, Wfc, bfc, pred, nNodes, 2);
}

// round 4
// speedup vs baseline: 1.9004x; 1.9004x over previous
#include <cuda_runtime.h>

#define CH 64
#define NMAX 100000
#define EMAX 1200000
#define SCAN_B 1024

// Scratch (allocation-free rule: __device__ globals)
__device__ float g_h1[NMAX * CH];
__device__ float g_mean[NMAX * CH];
__device__ int   g_deg[NMAX];
__device__ int   g_cur[NMAX];
__device__ int   g_rowptr[NMAX + 1];
__device__ int   g_csr[EMAX];
__device__ int   g_bsum[128];
__device__ int   g_boff[128];
__device__ int   g_is64;

// ---------------------------------------------------------------------------
// f32x2 packed helpers (Blackwell sm_103a: FFMA2 is PTX-only, never auto-fused)
// ---------------------------------------------------------------------------
__device__ __forceinline__ unsigned long long pk2(float lo, float hi) {
    unsigned long long r;
    asm("mov.b64 %0, {%1, %2};" : "=l"(r) : "f"(lo), "f"(hi));
    return r;
}
__device__ __forceinline__ unsigned long long dup2(float v) {
    unsigned long long r;
    asm("mov.b64 %0, {%1, %1};" : "=l"(r) : "f"(v));
    return r;
}
__device__ __forceinline__ void fma2(unsigned long long& d,
                                     unsigned long long a,
                                     unsigned long long b) {
    asm("fma.rn.f32x2 %0, %1, %2, %0;" : "+l"(d) : "l"(a), "l"(b));
}
__device__ __forceinline__ float2 up2(unsigned long long v) {
    float2 r;
    asm("mov.b64 {%0, %1}, %2;" : "=f"(r.x), "=f"(r.y) : "l"(v));
    return r;
}

// ---------------------------------------------------------------------------
// Detect int64 vs int32 edge_index. int32 data read as int64 pairs gives
// values >= nNodes unless the odd word is 0 (p ~ 1e-5 per sample, ^1024 ~ 0).
// ---------------------------------------------------------------------------
__global__ void detect_idx_kernel(const void* idx, int nNodes) {
    if (threadIdx.x == 0 && blockIdx.x == 0) {
        const long long* p = (const long long*)idx;
        int is64 = 1;
        for (int i = 0; i < 1024; i++) {
            long long v = p[i];
            if (v < 0 || v >= (long long)nNodes) { is64 = 0; break; }
        }
        g_is64 = is64;
    }
}

__global__ void zero_int_kernel(int n) {
    int i = blockIdx.x * blockDim.x + threadIdx.x;
    if (i < n) { g_deg[i] = 0; g_cur[i] = 0; }
}

__device__ __forceinline__ void load_edge(const void* idx, int nEdges, int e,
                                          int& s, int& d) {
    if (g_is64) {
        const long long* p = (const long long*)idx;
        s = (int)p[e];
        d = (int)p[nEdges + e];
    } else {
        const int* p = (const int*)idx;
        s = p[e];
        d = p[nEdges + e];
    }
}

__global__ void count_kernel(const void* __restrict__ idx, int nEdges) {
    int e = blockIdx.x * blockDim.x + threadIdx.x;
    if (e >= nEdges) return;
    int s, d;
    load_edge(idx, nEdges, e, s, d);
    atomicAdd(&g_deg[d], 1);
}

// ---- 3-phase exclusive scan of g_deg into g_rowptr -------------------------
__global__ void scan_block_kernel(int n) {
    __shared__ int sh[SCAN_B];
    int i = blockIdx.x * SCAN_B + threadIdx.x;
    int v = (i < n) ? g_deg[i] : 0;
    sh[threadIdx.x] = v;
    __syncthreads();
    for (int off = 1; off < SCAN_B; off <<= 1) {
        int t = (threadIdx.x >= off) ? sh[threadIdx.x - off] : 0;
        __syncthreads();
        sh[threadIdx.x] += t;
        __syncthreads();
    }
    if (i < n) g_rowptr[i] = sh[threadIdx.x] - v;
    if (threadIdx.x == SCAN_B - 1) g_bsum[blockIdx.x] = sh[SCAN_B - 1];
}

__global__ void scan_top_kernel(int nBlocks, int nEdges, int nNodes) {
    if (threadIdx.x == 0 && blockIdx.x == 0) {
        int run = 0;
        for (int b = 0; b < nBlocks; b++) {
            g_boff[b] = run;
            run += g_bsum[b];
        }
        g_rowptr[nNodes] = nEdges;
    }
}

__global__ void scan_add_kernel(int n) {
    int i = blockIdx.x * SCAN_B + threadIdx.x;
    if (i < n) g_rowptr[i] += g_boff[blockIdx.x];
}

__global__ void fill_kernel(const void* __restrict__ idx, int nEdges) {
    int e = blockIdx.x * blockDim.x + threadIdx.x;
    if (e >= nEdges) return;
    int s, d;
    load_edge(idx, nEdges, e, s, d);
    int pos = atomicAdd(&g_cur[d], 1);
    g_csr[g_rowptr[d] + pos] = s;
}

// ---------------------------------------------------------------------------
// Aggregate: warp per node. Lane owns channels (2*lane, 2*lane+1).
// mean[node] = (1/max(deg,1)) * sum_{s in CSR[node]} feat[s]
// CSR indices batch-loaded lane-parallel, broadcast via shfl; x4 unroll gives
// MLP=4 independent 8B loads per lane. No float atomics anywhere.
// ---------------------------------------------------------------------------
__global__ void __launch_bounds__(256)
aggregate_kernel(const float* __restrict__ feat, int nNodes, int nanFix) {
    int node = blockIdx.x * 8 + (threadIdx.x >> 5);
    int lane = threadIdx.x & 31;
    if (node >= nNodes) return;

    int r0 = g_rowptr[node];
    int r1 = g_rowptr[node + 1];
    const float2* f2 = (const float2*)feat;

    float ax = 0.0f, ay = 0.0f;
    for (int base = r0; base < r1; base += 32) {
        int cnt = min(32, r1 - base);
        int sidx = (base + lane < r1) ? g_csr[base + lane] : 0;
        int i = 0;
        for (; i + 4 <= cnt; i += 4) {
            int s0 = __shfl_sync(0xffffffffu, sidx, i);
            int s1 = __shfl_sync(0xffffffffu, sidx, i + 1);
            int s2 = __shfl_sync(0xffffffffu, sidx, i + 2);
            int s3 = __shfl_sync(0xffffffffu, sidx, i + 3);
            float2 v0 = f2[(size_t)s0 * 32 + lane];
            float2 v1 = f2[(size_t)s1 * 32 + lane];
            float2 v2 = f2[(size_t)s2 * 32 + lane];
            float2 v3 = f2[(size_t)s3 * 32 + lane];
            if (nanFix) {
                if (v0.x != v0.x) v0.x = 0.0f;
                if (v0.y != v0.y) v0.y = 0.0f;
                if (v1.x != v1.x) v1.x = 0.0f;
                if (v1.y != v1.y) v1.y = 0.0f;
                if (v2.x != v2.x) v2.x = 0.0f;
                if (v2.y != v2.y) v2.y = 0.0f;
                if (v3.x != v3.x) v3.x = 0.0f;
                if (v3.y != v3.y) v3.y = 0.0f;
            }
            ax += (v0.x + v1.x) + (v2.x + v3.x);
            ay += (v0.y + v1.y) + (v2.y + v3.y);
        }
        for (; i < cnt; i++) {
            int s = __shfl_sync(0xffffffffu, sidx, i);
            float2 v = f2[(size_t)s * 32 + lane];
            if (nanFix) {
                if (v.x != v.x) v.x = 0.0f;
                if (v.y != v.y) v.y = 0.0f;
            }
            ax += v.x;
            ay += v.y;
        }
    }

    int deg = r1 - r0;
    float inv = 1.0f / (float)((deg > 1) ? deg : 1);
    float2 out;
    out.x = ax * inv;
    out.y = ay * inv;
    ((float2*)g_mean)[(size_t)node * 32 + lane] = out;
}

// ---------------------------------------------------------------------------
// GEMM: H = relu(bias + mean @ Wl + x @ Wr)   [M=128 nodes/block, N=K=64]
// Thread (g = tid>>3, jg = tid&7): owns 4 nodes x 8 output channels.
// A (mean, x) lives entirely in registers: thread jg holds k-slice
// [jg*8, jg*8+8); per-k exchange via __shfl_sync (srcLane = (lane&24)|(k>>3)).
// Accumulate in packed f32x2 (FFMA2): per k-step 32 FMA2 + 8 LDS.64(W) +
// 8 shfl + 8 dup = 56 issue slots < 64-cycle FMA2 floor -> FMA2-rate-bound.
// layer 2 fuses pred = relu(H) @ Wfc + bfc (H never stored).
// ---------------------------------------------------------------------------
__global__ void __launch_bounds__(256)
gemm_kernel(const float* __restrict__ mean,
            const float* __restrict__ xsrc,
            const float* __restrict__ Wl,
            const float* __restrict__ bias,
            const float* __restrict__ Wr,
            const float* __restrict__ Wfc,
            const float* __restrict__ bfc,
            float* __restrict__ pred,
            int nNodes, int layer) {
    __shared__ float sWl[CH * CH];
    __shared__ float sWr[CH * CH];
    {
        const float4* wl4 = (const float4*)Wl;
        const float4* wr4 = (const float4*)Wr;
        float4* sl4 = (float4*)sWl;
        float4* sr4 = (float4*)sWr;
        for (int i = threadIdx.x; i < CH * CH / 4; i += 256) {
            sl4[i] = wl4[i];
            sr4[i] = wr4[i];
        }
    }
    __syncthreads();

    int tid = threadIdx.x;
    int lane = tid & 31;
    int jg = tid & 7;
    int j0 = jg * 8;
    int g = tid >> 3;
    int nodeBase = blockIdx.x * 128 + g * 4;

    // Register-resident A slices (each mean/x element loaded once per block)
    float aM[4][8], aX[4][8];
#pragma unroll
    for (int i = 0; i < 4; i++) {
        int node = nodeBase + i;
        if (node < nNodes) {
            const float4* pm = (const float4*)(mean + (size_t)node * CH + j0);
            float4 m0 = pm[0], m1 = pm[1];
            const float4* px = (const float4*)(xsrc + (size_t)node * CH + j0);
            float4 x0 = px[0], x1 = px[1];
            if (layer == 1) {
                if (x0.x != x0.x) x0.x = 0.0f;
                if (x0.y != x0.y) x0.y = 0.0f;
                if (x0.z != x0.z) x0.z = 0.0f;
                if (x0.w != x0.w) x0.w = 0.0f;
                if (x1.x != x1.x) x1.x = 0.0f;
                if (x1.y != x1.y) x1.y = 0.0f;
                if (x1.z != x1.z) x1.z = 0.0f;
                if (x1.w != x1.w) x1.w = 0.0f;
            }
            aM[i][0] = m0.x; aM[i][1] = m0.y; aM[i][2] = m0.z; aM[i][3] = m0.w;
            aM[i][4] = m1.x; aM[i][5] = m1.y; aM[i][6] = m1.z; aM[i][7] = m1.w;
            aX[i][0] = x0.x; aX[i][1] = x0.y; aX[i][2] = x0.z; aX[i][3] = x0.w;
            aX[i][4] = x1.x; aX[i][5] = x1.y; aX[i][6] = x1.z; aX[i][7] = x1.w;
        } else {
#pragma unroll
            for (int u = 0; u < 8; u++) { aM[i][u] = 0.0f; aX[i][u] = 0.0f; }
        }
    }

    // Accumulators (4 nodes x 4 channel-pairs), init with bias
    unsigned long long acc[4][4];
    {
        float4 b0 = *(const float4*)(bias + j0);
        float4 b1 = *(const float4*)(bias + j0 + 4);
        unsigned long long p0 = pk2(b0.x, b0.y);
        unsigned long long p1 = pk2(b0.z, b0.w);
        unsigned long long p2 = pk2(b1.x, b1.y);
        unsigned long long p3 = pk2(b1.z, b1.w);
#pragma unroll
        for (int i = 0; i < 4; i++) {
            acc[i][0] = p0; acc[i][1] = p1; acc[i][2] = p2; acc[i][3] = p3;
        }
    }

#pragma unroll
    for (int k = 0; k < CH; k++) {
        int srcLane = (lane & 24) | (k >> 3);
        const int r = k & 7;

        float m0 = __shfl_sync(0xffffffffu, aM[0][r], srcLane);
        float m1 = __shfl_sync(0xffffffffu, aM[1][r], srcLane);
        float m2 = __shfl_sync(0xffffffffu, aM[2][r], srcLane);
        float m3 = __shfl_sync(0xffffffffu, aM[3][r], srcLane);
        float x0 = __shfl_sync(0xffffffffu, aX[0][r], srcLane);
        float x1 = __shfl_sync(0xffffffffu, aX[1][r], srcLane);
        float x2 = __shfl_sync(0xffffffffu, aX[2][r], srcLane);
        float x3 = __shfl_sync(0xffffffffu, aX[3][r], srcLane);

        const unsigned long long* wl2 =
            (const unsigned long long*)&sWl[k * CH + j0];
        const unsigned long long* wr2 =
            (const unsigned long long*)&sWr[k * CH + j0];
        unsigned long long wl_0 = wl2[0], wl_1 = wl2[1];
        unsigned long long wl_2 = wl2[2], wl_3 = wl2[3];
        unsigned long long wr_0 = wr2[0], wr_1 = wr2[1];
        unsigned long long wr_2 = wr2[2], wr_3 = wr2[3];

        unsigned long long md0 = dup2(m0), md1 = dup2(m1);
        unsigned long long md2 = dup2(m2), md3 = dup2(m3);
        unsigned long long xd0 = dup2(x0), xd1 = dup2(x1);
        unsigned long long xd2 = dup2(x2), xd3 = dup2(x3);

        fma2(acc[0][0], md0, wl_0); fma2(acc[0][1], md0, wl_1);
        fma2(acc[0][2], md0, wl_2); fma2(acc[0][3], md0, wl_3);
        fma2(acc[0][0], xd0, wr_0); fma2(acc[0][1], xd0, wr_1);
        fma2(acc[0][2], xd0, wr_2); fma2(acc[0][3], xd0, wr_3);

        fma2(acc[1][0], md1, wl_0); fma2(acc[1][1], md1, wl_1);
        fma2(acc[1][2], md1, wl_2); fma2(acc[1][3], md1, wl_3);
        fma2(acc[1][0], xd1, wr_0); fma2(acc[1][1], xd1, wr_1);
        fma2(acc[1][2], xd1, wr_2); fma2(acc[1][3], xd1, wr_3);

        fma2(acc[2][0], md2, wl_0); fma2(acc[2][1], md2, wl_1);
        fma2(acc[2][2], md2, wl_2); fma2(acc[2][3], md2, wl_3);
        fma2(acc[2][0], xd2, wr_0); fma2(acc[2][1], xd2, wr_1);
        fma2(acc[2][2], xd2, wr_2); fma2(acc[2][3], xd2, wr_3);

        fma2(acc[3][0], md3, wl_0); fma2(acc[3][1], md3, wl_1);
        fma2(acc[3][2], md3, wl_2); fma2(acc[3][3], md3, wl_3);
        fma2(acc[3][0], xd3, wr_0); fma2(acc[3][1], xd3, wr_1);
        fma2(acc[3][2], xd3, wr_2); fma2(acc[3][3], xd3, wr_3);
    }

    if (layer == 1) {
#pragma unroll
        for (int i = 0; i < 4; i++) {
            int node = nodeBase + i;
            if (node < nNodes) {
                float2 c0 = up2(acc[i][0]);
                float2 c1 = up2(acc[i][1]);
                float2 c2 = up2(acc[i][2]);
                float2 c3 = up2(acc[i][3]);
                float4 o0 = make_float4(fmaxf(c0.x, 0.0f), fmaxf(c0.y, 0.0f),
                                        fmaxf(c1.x, 0.0f), fmaxf(c1.y, 0.0f));
                float4 o1 = make_float4(fmaxf(c2.x, 0.0f), fmaxf(c2.y, 0.0f),
                                        fmaxf(c3.x, 0.0f), fmaxf(c3.y, 0.0f));
                float4* po = (float4*)(g_h1 + (size_t)node * CH + j0);
                po[0] = o0;
                po[1] = o1;
            }
        }
    } else {
        float4 wf0 = *(const float4*)(Wfc + j0);
        float4 wf1 = *(const float4*)(Wfc + j0 + 4);
        float bf = bfc[0];
#pragma unroll
        for (int i = 0; i < 4; i++) {
            float2 c0 = up2(acc[i][0]);
            float2 c1 = up2(acc[i][1]);
            float2 c2 = up2(acc[i][2]);
            float2 c3 = up2(acc[i][3]);
            float p = fmaxf(c0.x, 0.0f) * wf0.x + fmaxf(c0.y, 0.0f) * wf0.y +
                      fmaxf(c1.x, 0.0f) * wf0.z + fmaxf(c1.y, 0.0f) * wf0.w +
                      fmaxf(c2.x, 0.0f) * wf1.x + fmaxf(c2.y, 0.0f) * wf1.y +
                      fmaxf(c3.x, 0.0f) * wf1.z + fmaxf(c3.y, 0.0f) * wf1.w;
            p += __shfl_down_sync(0xffffffffu, p, 4, 8);
            p += __shfl_down_sync(0xffffffffu, p, 2, 8);
            p += __shfl_down_sync(0xffffffffu, p, 1, 8);
            int node = nodeBase + i;
            if (jg == 0 && node < nNodes) pred[node] = p + bf;
        }
    }
}

// ---------------------------------------------------------------------------
// Launch (graph-capturable: kernel launches only; cudaGetSymbolAddress is a
// query, not a stream op or allocation)
// ---------------------------------------------------------------------------
extern "C" void kernel_launch(void* const* d_in, const int* in_sizes, int n_in,
                              void* d_out, int out_size) {
    const float* x   = (const float*)d_in[0];
    const void*  eix = d_in[1];
    const float* W1l = (const float*)d_in[2];
    const float* b1  = (const float*)d_in[3];
    const float* W1r = (const float*)d_in[4];
    const float* W2l = (const float*)d_in[5];
    const float* b2  = (const float*)d_in[6];
    const float* W2r = (const float*)d_in[7];
    const float* Wfc = (const float*)d_in[8];
    const float* bfc = (const float*)d_in[9];
    float* pred = (float*)d_out;

    int nNodes = in_sizes[0] / CH;   // 100000
    int nEdges = in_sizes[1] / 2;    // 1200000

    int edgeBlocks = (nEdges + 255) / 256;
    int nodeBlocks = (nNodes + 255) / 256;
    int scanBlocks = (nNodes + SCAN_B - 1) / SCAN_B;
    int aggBlocks  = (nNodes + 7) / 8;
    int gemmBlocks = (nNodes + 127) / 128;

    float* d_mean;
    cudaGetSymbolAddress((void**)&d_mean, g_mean);
    float* d_h1;
    cudaGetSymbolAddress((void**)&d_h1, g_h1);

    detect_idx_kernel<<<1, 32>>>(eix, nNodes);

    // Build CSR (dst -> list of src), reused by both layers
    zero_int_kernel<<<nodeBlocks, 256>>>(nNodes);
    count_kernel<<<edgeBlocks, 256>>>(eix, nEdges);
    scan_block_kernel<<<scanBlocks, SCAN_B>>>(nNodes);
    scan_top_kernel<<<1, 32>>>(scanBlocks, nEdges, nNodes);
    scan_add_kernel<<<scanBlocks, SCAN_B>>>(nNodes);
    fill_kernel<<<edgeBlocks, 256>>>(eix, nEdges);

    // Layer 1
    aggregate_kernel<<<aggBlocks, 256>>>(x, nNodes, /*nanFix=*/1);
    gemm_kernel<<<gemmBlocks, 256>>>(d_mean, x, W1l, b1, W1r,
                                     Wfc, bfc, pred, nNodes, 1);
    // Layer 2 (+ fused fc head)
    aggregate_kernel<<<aggBlocks, 256>>>(d_h1, nNodes, /*nanFix=*/0);
    gemm_kernel<<<gemmBlocks, 256>>>(d_mean, d_h1, W2l, b2, W2r,
                                     Wfc, bfc, pred, nNodes, 2);
}

// round 10
// speedup vs baseline: 1.9416x; 1.0217x over previous
#include <cuda_runtime.h>

#define CH 64
#define NMAX 100000
#define EMAX 1200000
#define SCAN_B 1024

// Scratch (allocation-free rule: __device__ globals)
__device__ float g_h1[NMAX * CH];
__device__ float g_mean[NMAX * CH];
__device__ int   g_deg[NMAX];
__device__ int   g_cur[NMAX];
__device__ int   g_rowptr[NMAX + 1];
__device__ int   g_csr[EMAX];
__device__ int   g_bsum[128];
__device__ int   g_is64;

// ---------------------------------------------------------------------------
// f32x2 packed helpers (sm_103a: FFMA2 reachable only via PTX fma.rn.f32x2)
// ---------------------------------------------------------------------------
__device__ __forceinline__ unsigned long long pk2(float lo, float hi) {
    unsigned long long r;
    asm("mov.b64 %0, {%1, %2};" : "=l"(r) : "f"(lo), "f"(hi));
    return r;
}
__device__ __forceinline__ unsigned long long dup2(float v) {
    unsigned long long r;
    asm("mov.b64 %0, {%1, %1};" : "=l"(r) : "f"(v));
    return r;
}
__device__ __forceinline__ void fma2(unsigned long long& d,
                                     unsigned long long a,
                                     unsigned long long b) {
    asm("fma.rn.f32x2 %0, %1, %2, %0;" : "+l"(d) : "l"(a), "l"(b));
}
__device__ __forceinline__ float2 up2(unsigned long long v) {
    float2 r;
    asm("mov.b64 {%0, %1}, %2;" : "=f"(r.x), "=f"(r.y) : "l"(v));
    return r;
}

// ---------------------------------------------------------------------------
// Fused: zero g_deg + detect int64 vs int32 edge_index (block 0, thread 0).
// int32 data read as int64 pairs gives values >= nNodes w.p. ~1 over 1024.
// ---------------------------------------------------------------------------
__global__ void init_kernel(const void* idx, int nNodes) {
    int i = blockIdx.x * blockDim.x + threadIdx.x;
    if (i < nNodes) g_deg[i] = 0;
    if (i == 0) {
        const long long* p = (const long long*)idx;
        int is64 = 1;
        for (int t = 0; t < 1024; t++) {
            long long v = p[t];
            if (v < 0 || v >= (long long)nNodes) { is64 = 0; break; }
        }
        g_is64 = is64;
    }
}

__device__ __forceinline__ void load_edge(const void* idx, int nEdges, int e,
                                          int& s, int& d) {
    if (g_is64) {
        const long long* p = (const long long*)idx;
        s = (int)p[e];
        d = (int)p[nEdges + e];
    } else {
        const int* p = (const int*)idx;
        s = p[e];
        d = p[nEdges + e];
    }
}

__global__ void count_kernel(const void* __restrict__ idx, int nEdges) {
    int e = blockIdx.x * blockDim.x + threadIdx.x;
    if (e >= nEdges) return;
    int s, d;
    load_edge(idx, nEdges, e, s, d);
    atomicAdd(&g_deg[d], 1);
}

// ---- 2-phase exclusive scan of g_deg into g_rowptr -------------------------
__global__ void scan_block_kernel(int n) {
    __shared__ int sh[SCAN_B];
    int i = blockIdx.x * SCAN_B + threadIdx.x;
    int v = (i < n) ? g_deg[i] : 0;
    sh[threadIdx.x] = v;
    __syncthreads();
    for (int off = 1; off < SCAN_B; off <<= 1) {
        int t = (threadIdx.x >= off) ? sh[threadIdx.x - off] : 0;
        __syncthreads();
        sh[threadIdx.x] += t;
        __syncthreads();
    }
    if (i < n) g_rowptr[i] = sh[threadIdx.x] - v;   // block-local exclusive
    if (threadIdx.x == SCAN_B - 1) g_bsum[blockIdx.x] = sh[SCAN_B - 1];
}

// Each block warp-reduces its own prefix of g_bsum (<=128 values), then adds.
// Also pre-initializes g_cur = rowptr so fill_kernel needs no rowptr read,
// and writes the rowptr sentinel. Replaces scan_top + scan_add (one launch).
__global__ void scan_finish_kernel(int n, int nEdges) {
    __shared__ int sOff;
    if (threadIdx.x < 32) {
        int acc = 0;
        for (int b = threadIdx.x; b < blockIdx.x; b += 32) acc += g_bsum[b];
#pragma unroll
        for (int o = 16; o > 0; o >>= 1)
            acc += __shfl_down_sync(0xffffffffu, acc, o);
        if (threadIdx.x == 0) sOff = acc;
    }
    __syncthreads();
    int i = blockIdx.x * SCAN_B + threadIdx.x;
    if (i < n) {
        int v = g_rowptr[i] + sOff;
        g_rowptr[i] = v;
        g_cur[i] = v;
    }
    if (i == 0) g_rowptr[n] = nEdges;
}

__global__ void fill_kernel(const void* __restrict__ idx, int nEdges) {
    int e = blockIdx.x * blockDim.x + threadIdx.x;
    if (e >= nEdges) return;
    int s, d;
    load_edge(idx, nEdges, e, s, d);
    int pos = atomicAdd(&g_cur[d], 1);   // g_cur pre-init to rowptr
    g_csr[pos] = s;
}

// ---------------------------------------------------------------------------
// Aggregate: warp per node; lane owns channels (2*lane, 2*lane+1).
// mean[node] = (1/max(deg,1)) * sum_{s in CSR[node]} feat[s]
// 8-wide masked batches: out-of-range slots read node 0's row (safe) and are
// zeroed via FSEL masks -> MLP=8 always, no serial scalar tail.
// ---------------------------------------------------------------------------
__global__ void __launch_bounds__(256)
aggregate_kernel(const float* __restrict__ feat, int nNodes, int nanFix) {
    int node = blockIdx.x * 8 + (threadIdx.x >> 5);
    int lane = threadIdx.x & 31;
    if (node >= nNodes) return;

    int r0 = g_rowptr[node];
    int r1 = g_rowptr[node + 1];
    const float2* f2 = (const float2*)feat;

    float ax = 0.0f, ay = 0.0f;
    for (int base = r0; base < r1; base += 32) {
        int cnt = min(32, r1 - base);
        int sidx = (base + lane < r1) ? g_csr[base + lane] : 0;
        for (int i = 0; i < cnt; i += 8) {
            int s0 = __shfl_sync(0xffffffffu, sidx, i);
            int s1 = __shfl_sync(0xffffffffu, sidx, i + 1);
            int s2 = __shfl_sync(0xffffffffu, sidx, i + 2);
            int s3 = __shfl_sync(0xffffffffu, sidx, i + 3);
            int s4 = __shfl_sync(0xffffffffu, sidx, i + 4);
            int s5 = __shfl_sync(0xffffffffu, sidx, i + 5);
            int s6 = __shfl_sync(0xffffffffu, sidx, i + 6);
            int s7 = __shfl_sync(0xffffffffu, sidx, i + 7);
            float2 v0 = f2[(size_t)s0 * 32 + lane];
            float2 v1 = f2[(size_t)s1 * 32 + lane];
            float2 v2 = f2[(size_t)s2 * 32 + lane];
            float2 v3 = f2[(size_t)s3 * 32 + lane];
            float2 v4 = f2[(size_t)s4 * 32 + lane];
            float2 v5 = f2[(size_t)s5 * 32 + lane];
            float2 v6 = f2[(size_t)s6 * 32 + lane];
            float2 v7 = f2[(size_t)s7 * 32 + lane];
            // mask out-of-range slots (slot 0 always valid since i < cnt)
            float m1 = (i + 1 < cnt) ? 1.0f : 0.0f;
            float m2 = (i + 2 < cnt) ? 1.0f : 0.0f;
            float m3 = (i + 3 < cnt) ? 1.0f : 0.0f;
            float m4 = (i + 4 < cnt) ? 1.0f : 0.0f;
            float m5 = (i + 5 < cnt) ? 1.0f : 0.0f;
            float m6 = (i + 6 < cnt) ? 1.0f : 0.0f;
            float m7 = (i + 7 < cnt) ? 1.0f : 0.0f;
            if (nanFix) {
                if (v0.x != v0.x) v0.x = 0.0f;
                if (v0.y != v0.y) v0.y = 0.0f;
                if (v1.x != v1.x) v1.x = 0.0f;
                if (v1.y != v1.y) v1.y = 0.0f;
                if (v2.x != v2.x) v2.x = 0.0f;
                if (v2.y != v2.y) v2.y = 0.0f;
                if (v3.x != v3.x) v3.x = 0.0f;
                if (v3.y != v3.y) v3.y = 0.0f;
                if (v4.x != v4.x) v4.x = 0.0f;
                if (v4.y != v4.y) v4.y = 0.0f;
                if (v5.x != v5.x) v5.x = 0.0f;
                if (v5.y != v5.y) v5.y = 0.0f;
                if (v6.x != v6.x) v6.x = 0.0f;
                if (v6.y != v6.y) v6.y = 0.0f;
                if (v7.x != v7.x) v7.x = 0.0f;
                if (v7.y != v7.y) v7.y = 0.0f;
            }
            ax += v0.x + m1 * v1.x + m2 * v2.x + m3 * v3.x
                + m4 * v4.x + m5 * v5.x + m6 * v6.x + m7 * v7.x;
            ay += v0.y + m1 * v1.y + m2 * v2.y + m3 * v3.y
                + m4 * v4.y + m5 * v5.y + m6 * v6.y + m7 * v7.y;
        }
    }

    int deg = r1 - r0;
    float inv = 1.0f / (float)((deg > 1) ? deg : 1);
    float2 out;
    out.x = ax * inv;
    out.y = ay * inv;
    ((float2*)g_mean)[(size_t)node * 32 + lane] = out;
}

// ---------------------------------------------------------------------------
// GEMM: H = relu(bias + mean @ Wl + x @ Wr)   [M=64 nodes/block, N=K=64]
// 128-thread blocks (16 groups x 4 nodes): ~130 regs/thread -> 3 blocks/SM
// (12 warps, 3/SMSP) for latency hiding vs 2/SMSP at 256 threads.
// A (mean, x) register-resident, exchanged per-k via shfl. Weights in smem
// read as LDS.128 (longlong2). Accumulate in packed f32x2 (FFMA2).
// layer 2 fuses pred = relu(H) @ Wfc + bfc (H never stored).
// ---------------------------------------------------------------------------
__global__ void __launch_bounds__(128)
gemm_kernel(const float* __restrict__ mean,
            const float* __restrict__ xsrc,
            const float* __restrict__ Wl,
            const float* __restrict__ bias,
            const float* __restrict__ Wr,
            const float* __restrict__ Wfc,
            const float* __restrict__ bfc,
            float* __restrict__ pred,
            int nNodes, int layer) {
    __shared__ float sWl[CH * CH];
    __shared__ float sWr[CH * CH];
    {
        const float4* wl4 = (const float4*)Wl;
        const float4* wr4 = (const float4*)Wr;
        float4* sl4 = (float4*)sWl;
        float4* sr4 = (float4*)sWr;
        for (int i = threadIdx.x; i < CH * CH / 4; i += 128) {
            sl4[i] = wl4[i];
            sr4[i] = wr4[i];
        }
    }
    __syncthreads();

    int tid = threadIdx.x;
    int lane = tid & 31;
    int jg = tid & 7;
    int j0 = jg * 8;
    int g = tid >> 3;                       // 0..15
    int nodeBase = blockIdx.x * 64 + g * 4;

    // Register-resident A slices (thread jg holds k-slice [jg*8, jg*8+8))
    float aM[4][8], aX[4][8];
#pragma unroll
    for (int i = 0; i < 4; i++) {
        int node = nodeBase + i;
        if (node < nNodes) {
            const float4* pm = (const float4*)(mean + (size_t)node * CH + j0);
            float4 m0 = pm[0], m1 = pm[1];
            const float4* px = (const float4*)(xsrc + (size_t)node * CH + j0);
            float4 x0 = px[0], x1 = px[1];
            if (layer == 1) {
                if (x0.x != x0.x) x0.x = 0.0f;
                if (x0.y != x0.y) x0.y = 0.0f;
                if (x0.z != x0.z) x0.z = 0.0f;
                if (x0.w != x0.w) x0.w = 0.0f;
                if (x1.x != x1.x) x1.x = 0.0f;
                if (x1.y != x1.y) x1.y = 0.0f;
                if (x1.z != x1.z) x1.z = 0.0f;
                if (x1.w != x1.w) x1.w = 0.0f;
            }
            aM[i][0] = m0.x; aM[i][1] = m0.y; aM[i][2] = m0.z; aM[i][3] = m0.w;
            aM[i][4] = m1.x; aM[i][5] = m1.y; aM[i][6] = m1.z; aM[i][7] = m1.w;
            aX[i][0] = x0.x; aX[i][1] = x0.y; aX[i][2] = x0.z; aX[i][3] = x0.w;
            aX[i][4] = x1.x; aX[i][5] = x1.y; aX[i][6] = x1.z; aX[i][7] = x1.w;
        } else {
#pragma unroll
            for (int u = 0; u < 8; u++) { aM[i][u] = 0.0f; aX[i][u] = 0.0f; }
        }
    }

    // Accumulators (4 nodes x 4 channel-pairs), init with bias
    unsigned long long acc[4][4];
    {
        float4 b0 = *(const float4*)(bias + j0);
        float4 b1 = *(const float4*)(bias + j0 + 4);
        unsigned long long p0 = pk2(b0.x, b0.y);
        unsigned long long p1 = pk2(b0.z, b0.w);
        unsigned long long p2 = pk2(b1.x, b1.y);
        unsigned long long p3 = pk2(b1.z, b1.w);
#pragma unroll
        for (int i = 0; i < 4; i++) {
            acc[i][0] = p0; acc[i][1] = p1; acc[i][2] = p2; acc[i][3] = p3;
        }
    }

#pragma unroll
    for (int k = 0; k < CH; k++) {
        int srcLane = (lane & 24) | (k >> 3);
        const int r = k & 7;

        float m0 = __shfl_sync(0xffffffffu, aM[0][r], srcLane);
        float m1 = __shfl_sync(0xffffffffu, aM[1][r], srcLane);
        float m2 = __shfl_sync(0xffffffffu, aM[2][r], srcLane);
        float m3 = __shfl_sync(0xffffffffu, aM[3][r], srcLane);
        float x0 = __shfl_sync(0xffffffffu, aX[0][r], srcLane);
        float x1 = __shfl_sync(0xffffffffu, aX[1][r], srcLane);
        float x2 = __shfl_sync(0xffffffffu, aX[2][r], srcLane);
        float x3 = __shfl_sync(0xffffffffu, aX[3][r], srcLane);

        longlong2 wlA = *(const longlong2*)&sWl[k * CH + j0];
        longlong2 wlB = *(const longlong2*)&sWl[k * CH + j0 + 4];
        longlong2 wrA = *(const longlong2*)&sWr[k * CH + j0];
        longlong2 wrB = *(const longlong2*)&sWr[k * CH + j0 + 4];
        unsigned long long wl_0 = (unsigned long long)wlA.x;
        unsigned long long wl_1 = (unsigned long long)wlA.y;
        unsigned long long wl_2 = (unsigned long long)wlB.x;
        unsigned long long wl_3 = (unsigned long long)wlB.y;
        unsigned long long wr_0 = (unsigned long long)wrA.x;
        unsigned long long wr_1 = (unsigned long long)wrA.y;
        unsigned long long wr_2 = (unsigned long long)wrB.x;
        unsigned long long wr_3 = (unsigned long long)wrB.y;

        unsigned long long md0 = dup2(m0), md1 = dup2(m1);
        unsigned long long md2 = dup2(m2), md3 = dup2(m3);
        unsigned long long xd0 = dup2(x0), xd1 = dup2(x1);
        unsigned long long xd2 = dup2(x2), xd3 = dup2(x3);

        fma2(acc[0][0], md0, wl_0); fma2(acc[0][1], md0, wl_1);
        fma2(acc[0][2], md0, wl_2); fma2(acc[0][3], md0, wl_3);
        fma2(acc[0][0], xd0, wr_0); fma2(acc[0][1], xd0, wr_1);
        fma2(acc[0][2], xd0, wr_2); fma2(acc[0][3], xd0, wr_3);

        fma2(acc[1][0], md1, wl_0); fma2(acc[1][1], md1, wl_1);
        fma2(acc[1][2], md1, wl_2); fma2(acc[1][3], md1, wl_3);
        fma2(acc[1][0], xd1, wr_0); fma2(acc[1][1], xd1, wr_1);
        fma2(acc[1][2], xd1, wr_2); fma2(acc[1][3], xd1, wr_3);

        fma2(acc[2][0], md2, wl_0); fma2(acc[2][1], md2, wl_1);
        fma2(acc[2][2], md2, wl_2); fma2(acc[2][3], md2, wl_3);
        fma2(acc[2][0], xd2, wr_0); fma2(acc[2][1], xd2, wr_1);
        fma2(acc[2][2], xd2, wr_2); fma2(acc[2][3], xd2, wr_3);

        fma2(acc[3][0], md3, wl_0); fma2(acc[3][1], md3, wl_1);
        fma2(acc[3][2], md3, wl_2); fma2(acc[3][3], md3, wl_3);
        fma2(acc[3][0], xd3, wr_0); fma2(acc[3][1], xd3, wr_1);
        fma2(acc[3][2], xd3, wr_2); fma2(acc[3][3], xd3, wr_3);
    }

    if (layer == 1) {
#pragma unroll
        for (int i = 0; i < 4; i++) {
            int node = nodeBase + i;
            if (node < nNodes) {
                float2 c0 = up2(acc[i][0]);
                float2 c1 = up2(acc[i][1]);
                float2 c2 = up2(acc[i][2]);
                float2 c3 = up2(acc[i][3]);
                float4 o0 = make_float4(fmaxf(c0.x, 0.0f), fmaxf(c0.y, 0.0f),
                                        fmaxf(c1.x, 0.0f), fmaxf(c1.y, 0.0f));
                float4 o1 = make_float4(fmaxf(c2.x, 0.0f), fmaxf(c2.y, 0.0f),
                                        fmaxf(c3.x, 0.0f), fmaxf(c3.y, 0.0f));
                float4* po = (float4*)(g_h1 + (size_t)node * CH + j0);
                po[0] = o0;
                po[1] = o1;
            }
        }
    } else {
        float4 wf0 = *(const float4*)(Wfc + j0);
        float4 wf1 = *(const float4*)(Wfc + j0 + 4);
        float bf = bfc[0];
#pragma unroll
        for (int i = 0; i < 4; i++) {
            float2 c0 = up2(acc[i][0]);
            float2 c1 = up2(acc[i][1]);
            float2 c2 = up2(acc[i][2]);
            float2 c3 = up2(acc[i][3]);
            float p = fmaxf(c0.x, 0.0f) * wf0.x + fmaxf(c0.y, 0.0f) * wf0.y +
                      fmaxf(c1.x, 0.0f) * wf0.z + fmaxf(c1.y, 0.0f) * wf0.w +
                      fmaxf(c2.x, 0.0f) * wf1.x + fmaxf(c2.y, 0.0f) * wf1.y +
                      fmaxf(c3.x, 0.0f) * wf1.z + fmaxf(c3.y, 0.0f) * wf1.w;
            p += __shfl_down_sync(0xffffffffu, p, 4, 8);
            p += __shfl_down_sync(0xffffffffu, p, 2, 8);
            p += __shfl_down_sync(0xffffffffu, p, 1, 8);
            int node = nodeBase + i;
            if (jg == 0 && node < nNodes) pred[node] = p + bf;
        }
    }
}

// ---------------------------------------------------------------------------
// Launch (graph-capturable: kernel launches only; cudaGetSymbolAddress is a
// query, not a stream op or allocation). 9 launches total; ncu -s 5 -c 1 now
// profiles launch #6 = aggregate_kernel (layer 1).
// ---------------------------------------------------------------------------
extern "C" void kernel_launch(void* const* d_in, const int* in_sizes, int n_in,
                              void* d_out, int out_size) {
    const float* x   = (const float*)d_in[0];
    const void*  eix = d_in[1];
    const float* W1l = (const float*)d_in[2];
    const float* b1  = (const float*)d_in[3];
    const float* W1r = (const float*)d_in[4];
    const float* W2l = (const float*)d_in[5];
    const float* b2  = (const float*)d_in[6];
    const float* W2r = (const float*)d_in[7];
    const float* Wfc = (const float*)d_in[8];
    const float* bfc = (const float*)d_in[9];
    float* pred = (float*)d_out;

    int nNodes = in_sizes[0] / CH;   // 100000
    int nEdges = in_sizes[1] / 2;    // 1200000

    int edgeBlocks = (nEdges + 255) / 256;
    int nodeBlocks = (nNodes + 255) / 256;
    int scanBlocks = (nNodes + SCAN_B - 1) / SCAN_B;
    int aggBlocks  = (nNodes + 7) / 8;
    int gemmBlocks = (nNodes + 63) / 64;

    float* d_mean;
    cudaGetSymbolAddress((void**)&d_mean, g_mean);
    float* d_h1;
    cudaGetSymbolAddress((void**)&d_h1, g_h1);

    // Build CSR (dst -> list of src), reused by both layers
    init_kernel<<<nodeBlocks, 256>>>(eix, nNodes);             // 1
    count_kernel<<<edgeBlocks, 256>>>(eix, nEdges);            // 2
    scan_block_kernel<<<scanBlocks, SCAN_B>>>(nNodes);         // 3
    scan_finish_kernel<<<scanBlocks, SCAN_B>>>(nNodes, nEdges);// 4
    fill_kernel<<<edgeBlocks, 256>>>(eix, nEdges);             // 5

    // Layer 1
    aggregate_kernel<<<aggBlocks, 256>>>(x, nNodes, 1);        // 6 <- profiled
    gemm_kernel<<<gemmBlocks, 128>>>(d_mean, x, W1l, b1, W1r,
                                     Wfc, bfc, pred, nNodes, 1);  // 7
    // Layer 2 (+ fused fc head)
    aggregate_kernel<<<aggBlocks, 256>>>(d_h1, nNodes, 0);     // 8
    gemm_kernel<<<gemmBlocks, 128>>>(d_mean, d_h1, W2l, b2, W2r,
                                     Wfc, bfc, pred, nNodes, 2);  // 9
}